// round 13
// baseline (speedup 1.0000x reference)
#include <cuda_runtime.h>
#include <cuda_bf16.h>
#include <math.h>

// ---------------------------------------------------------------------------
// CrystalGraphAttention  (B=8, N=1024, D=256, H=8, dk=dv=64)
//
//   q,k,v = X @ W{q,k,v}   (kernel 1, bf16 3-term; 2-stage W staging)  [R12]
//   flash attention        (kernel 2, bf16 3-term; NO-MAX softmax;
//                           NEW: hi/lo-interleaved uint2 smem, V stride fixed
//                           36 (was 40 -> 2-way bank conflict on V B-frags))
//   out = ctx @ Wo + bo    (kernel 3, bf16 3-term; 4-stage W staging)  [R12]
// ---------------------------------------------------------------------------

#define NEGBIG (-1.0e9f)

static __device__ float g_q [8 * 8 * 1024 * 64];    // [B,H,N,64]
static __device__ float g_k [8 * 8 * 1024 * 64];
static __device__ float g_v [8 * 8 * 1024 * 64];
static __device__ float g_ctx[8 * 1024 * 512];      // [B*N, H*64]

// ---------------------------------------------------------------------------
#define MMA_BF16(c, a, b0, b1)                                              \
    asm volatile(                                                           \
        "mma.sync.aligned.m16n8k16.row.col.f32.bf16.bf16.f32 "              \
        "{%0,%1,%2,%3}, {%4,%5,%6,%7}, {%8,%9}, {%0,%1,%2,%3};"             \
        : "+f"((c)[0]), "+f"((c)[1]), "+f"((c)[2]), "+f"((c)[3])            \
        : "r"((a)[0]), "r"((a)[1]), "r"((a)[2]), "r"((a)[3]),               \
          "r"(b0), "r"(b1))

__device__ __forceinline__ unsigned pack_bf2(float x, float y)
{
    unsigned r;
    asm("cvt.rn.bf16x2.f32 %0, %1, %2;" : "=r"(r) : "f"(y), "f"(x));
    return r;
}

__device__ __forceinline__ float bf16_hi_f(float x)
{
    return __bfloat162float(__float2bfloat16(x));
}

// ---------------------------------------------------------------------------
// Kernel 1: QKV projection (R12 measured-best, ~81us).
// ---------------------------------------------------------------------------
__global__ __launch_bounds__(256, 2) void qkv_kernel(
    const float* __restrict__ X,
    const float* __restrict__ Wq,
    const float* __restrict__ Wk,
    const float* __restrict__ Wv)
{
    __shared__ __align__(16) unsigned Whi[64 * 72];
    __shared__ __align__(16) unsigned Wlo[64 * 72];

    const int tid  = threadIdx.x;
    const int wid  = tid >> 5;
    const int lane = tid & 31;
    const int g    = lane >> 2;
    const int tg   = lane & 3;
    const int mt = blockIdx.x, h = blockIdx.y, w = blockIdx.z;
    const float* W = (w == 0) ? Wq : (w == 1) ? Wk : Wv;
    float* Out     = (w == 0) ? g_q : (w == 1) ? g_k : g_v;

    const int mrow0 = mt * 128 + wid * 16;
    const float* arow0 = &X[(size_t)(mrow0 + g) * 256];
    const float* arow1 = arow0 + 8 * 256;

    const int kp  = tid >> 2;
    const int n16 = (tid & 3) * 16;

    float C[8][4];
    #pragma unroll
    for (int nt = 0; nt < 8; nt++)
        #pragma unroll
        for (int j = 0; j < 4; j++) C[nt][j] = 0.f;

    #pragma unroll
    for (int s = 0; s < 2; s++) {
        __syncthreads();
        {
            const float* wr0 = &W[(size_t)(s * 128 + 2 * kp) * 512 + h * 64 + n16];
            const float* wr1 = wr0 + 512;
            #pragma unroll
            for (int c = 0; c < 16; c += 4) {
                float4 w0 = *(const float4*)&wr0[c];
                float4 w1 = *(const float4*)&wr1[c];
                float h0x = bf16_hi_f(w0.x), h1x = bf16_hi_f(w1.x);
                float h0y = bf16_hi_f(w0.y), h1y = bf16_hi_f(w1.y);
                float h0z = bf16_hi_f(w0.z), h1z = bf16_hi_f(w1.z);
                float h0w = bf16_hi_f(w0.w), h1w = bf16_hi_f(w1.w);
                uint4 hi4, lo4;
                hi4.x = pack_bf2(h0x, h1x);
                hi4.y = pack_bf2(h0y, h1y);
                hi4.z = pack_bf2(h0z, h1z);
                hi4.w = pack_bf2(h0w, h1w);
                lo4.x = pack_bf2(w0.x - h0x, w1.x - h1x);
                lo4.y = pack_bf2(w0.y - h0y, w1.y - h1y);
                lo4.z = pack_bf2(w0.z - h0z, w1.z - h1z);
                lo4.w = pack_bf2(w0.w - h0w, w1.w - h1w);
                *(uint4*)&Whi[kp * 72 + n16 + c] = hi4;
                *(uint4*)&Wlo[kp * 72 + n16 + c] = lo4;
            }
        }
        __syncthreads();

        #pragma unroll
        for (int k0 = 0; k0 < 128; k0 += 32) {
            #pragma unroll
            for (int kc = 0; kc < 2; kc++) {
                unsigned ahi[4], alo[4];
                {
                    int col = s * 128 + k0 + kc * 16 + 2 * tg;
                    float2 a0 = *(const float2*)&arow0[col];
                    float2 a1 = *(const float2*)&arow1[col];
                    float2 a2 = *(const float2*)&arow0[col + 8];
                    float2 a3 = *(const float2*)&arow1[col + 8];
                    float hx, hy;
                    hx = bf16_hi_f(a0.x); hy = bf16_hi_f(a0.y);
                    ahi[0] = pack_bf2(hx, hy); alo[0] = pack_bf2(a0.x - hx, a0.y - hy);
                    hx = bf16_hi_f(a1.x); hy = bf16_hi_f(a1.y);
                    ahi[1] = pack_bf2(hx, hy); alo[1] = pack_bf2(a1.x - hx, a1.y - hy);
                    hx = bf16_hi_f(a2.x); hy = bf16_hi_f(a2.y);
                    ahi[2] = pack_bf2(hx, hy); alo[2] = pack_bf2(a2.x - hx, a2.y - hy);
                    hx = bf16_hi_f(a3.x); hy = bf16_hi_f(a3.y);
                    ahi[3] = pack_bf2(hx, hy); alo[3] = pack_bf2(a3.x - hx, a3.y - hy);
                }
                #pragma unroll
                for (int nt = 0; nt < 8; nt++) {
                    int base = (k0 / 2 + kc * 8 + tg) * 72 + nt * 8 + g;
                    unsigned b0h = Whi[base], b1h = Whi[base + 4 * 72];
                    unsigned b0l = Wlo[base], b1l = Wlo[base + 4 * 72];
                    MMA_BF16(C[nt], ahi, b0h, b1h);
                    MMA_BF16(C[nt], ahi, b0l, b1l);
                    MMA_BF16(C[nt], alo, b0h, b1h);
                }
            }
        }
    }

    #pragma unroll
    for (int nt = 0; nt < 8; nt++) {
        int m0 = mrow0 + g;
        int m1 = m0 + 8;
        int b0i = m0 >> 10, s0 = m0 & 1023;
        int b1i = m1 >> 10, s1 = m1 & 1023;
        float2 r0, r1;
        r0.x = C[nt][0]; r0.y = C[nt][1];
        r1.x = C[nt][2]; r1.y = C[nt][3];
        *(float2*)&Out[(size_t)((b0i * 8 + h) * 1024 + s0) * 64 + nt * 8 + 2 * tg] = r0;
        *(float2*)&Out[(size_t)((b1i * 8 + h) * 1024 + s1) * 64 + nt * 8 + 2 * tg] = r1;
    }
}

// ---------------------------------------------------------------------------
// Kernel 2: flash attention, bf16 3-term, NO-MAX softmax.
// NEW: hi/lo interleaved uint2 smem tiles, stride 36 uint2 (conflict-free
// reads AND writes for both K and Vt; V was 2-way conflicted before).
// grid = (8 qtiles, 8 heads, 8 batches), block = 256 (8 warps).
// ---------------------------------------------------------------------------
__global__ __launch_bounds__(256, 2) void attn_kernel(
    const float* __restrict__ em,     // [B,1,N,N]
    const float* __restrict__ dw)     // [B,N]
{
    __shared__ __align__(16) uint2 Ks2[64 * 36];   // [key][dpair] = (hi,lo)
    __shared__ __align__(16) uint2 Vt2[64 * 36];   // [d][keypair] = (hi,lo)

    const int tid  = threadIdx.x;
    const int wid  = tid >> 5;
    const int lane = tid & 31;
    const int g    = lane >> 2;
    const int tg   = lane & 3;
    const int qt = blockIdx.x, h = blockIdx.y, b = blockIdx.z;
    const int qrow0 = qt * 128 + wid * 16;

    const float* qb = &g_q[(size_t)((b * 8 + h) * 1024 + qrow0) * 64];
    const float* kb = &g_k[(size_t)(b * 8 + h) * 1024 * 64];
    const float* vb = &g_v[(size_t)(b * 8 + h) * 1024 * 64];
    const float* emb = em + (size_t)b * 1024 * 1024;
    const float* dwb = dw + b * 1024;

    // ---- Q fragments (scaled 1/8), packed bf16x2 hi/lo, resident ----
    unsigned qhi[4][4], qlo[4][4];
    #pragma unroll
    for (int kc = 0; kc < 4; kc++) {
        #pragma unroll
        for (int j = 0; j < 4; j++) {
            int row = (j & 1) ? g + 8 : g;
            int col = kc * 16 + 2 * tg + ((j >> 1) ? 8 : 0);
            float2 qv = *(const float2*)&qb[(size_t)row * 64 + col];
            qv.x *= 0.125f; qv.y *= 0.125f;
            float hx = bf16_hi_f(qv.x), hy = bf16_hi_f(qv.y);
            qhi[kc][j] = pack_bf2(hx, hy);
            qlo[kc][j] = pack_bf2(qv.x - hx, qv.y - hy);
        }
    }

    float O[8][4];
    #pragma unroll
    for (int nt = 0; nt < 8; nt++)
        #pragma unroll
        for (int j = 0; j < 4; j++) O[nt][j] = 0.f;
    float li0 = 0.f, li1 = 0.f;

    // staging maps
    const int kr  = tid >> 4;            // K: key row base (0..15)
    const int kc4 = (tid & 15) * 4;      // K: d base (dpair pair = kc4/2)
    const int vkp = tid & 31;            // V: keypair (0..31)
    const int vd0 = (tid >> 5) * 8;      // V: d group base

    unsigned* Ks2u = (unsigned*)Ks2;

    for (int kt = 0; kt < 16; kt++) {
        __syncthreads();
        // ---- stage K: [key][dpair] interleaved (hi,lo), uint4 writes ----
        {
            int r = kr;
            #pragma unroll
            for (int t = 0; t < 4; t++, r += 16) {
                float4 kv = *(const float4*)&kb[(size_t)(kt * 64 + r) * 64 + kc4];
                float h0 = bf16_hi_f(kv.x), h1 = bf16_hi_f(kv.y);
                float h2 = bf16_hi_f(kv.z), h3 = bf16_hi_f(kv.w);
                uint4 pk;
                pk.x = pack_bf2(h0, h1);                   // hi pair 0
                pk.y = pack_bf2(kv.x - h0, kv.y - h1);     // lo pair 0
                pk.z = pack_bf2(h2, h3);                   // hi pair 1
                pk.w = pack_bf2(kv.z - h2, kv.w - h3);     // lo pair 1
                *(uint4*)&Ks2u[r * 72 + kc4] = pk;
            }
        }
        // ---- stage V transposed: [d][keypair] interleaved (hi,lo) ----
        {
            const float* vr0 = &vb[(size_t)(kt * 64 + 2 * vkp) * 64 + vd0];
            const float* vr1 = vr0 + 64;
            float e0[8], e1[8];
            float4 t0 = *(const float4*)&vr0[0];
            float4 t1 = *(const float4*)&vr0[4];
            float4 u0 = *(const float4*)&vr1[0];
            float4 u1 = *(const float4*)&vr1[4];
            e0[0]=t0.x; e0[1]=t0.y; e0[2]=t0.z; e0[3]=t0.w;
            e0[4]=t1.x; e0[5]=t1.y; e0[6]=t1.z; e0[7]=t1.w;
            e1[0]=u0.x; e1[1]=u0.y; e1[2]=u0.z; e1[3]=u0.w;
            e1[4]=u1.x; e1[5]=u1.y; e1[6]=u1.z; e1[7]=u1.w;
            #pragma unroll
            for (int i = 0; i < 8; i++) {
                float h0 = bf16_hi_f(e0[i]), h1 = bf16_hi_f(e1[i]);
                uint2 pv;
                pv.x = pack_bf2(h0, h1);
                pv.y = pack_bf2(e0[i] - h0, e1[i] - h1);
                Vt2[(vd0 + i) * 36 + vkp] = pv;
            }
        }
        __syncthreads();

        // ---- S = (Q/8) K^T  (8 independent chains; uint2 B-frag loads) ----
        float S[8][4];
        #pragma unroll
        for (int nt = 0; nt < 8; nt++) {
            S[nt][0] = S[nt][1] = S[nt][2] = S[nt][3] = 0.f;
            #pragma unroll
            for (int kc = 0; kc < 4; kc++) {
                int base = (nt * 8 + g) * 36 + kc * 8 + tg;
                uint2 b0 = Ks2[base];
                uint2 b1 = Ks2[base + 4];
                MMA_BF16(S[nt], qhi[kc], b0.x, b1.x);
                MMA_BF16(S[nt], qhi[kc], b0.y, b1.y);
                MMA_BF16(S[nt], qlo[kc], b0.x, b1.x);
            }
        }

        // ---- mask + dw + exp (no max, no shuffles) ----
        const float* er0 = emb + (size_t)(qrow0 + g) * 1024 + kt * 64;
        const float* er1 = er0 + (size_t)8 * 1024;
        const float* dr  = dwb + kt * 64;
        #pragma unroll
        for (int nt = 0; nt < 8; nt++) {
            float2 m0v = *(const float2*)&er0[nt * 8 + 2 * tg];
            float2 m1v = *(const float2*)&er1[nt * 8 + 2 * tg];
            float2 dv  = *(const float2*)&dr [nt * 8 + 2 * tg];
            float p0 = __expf((S[nt][0] + (1.f - m0v.x) * NEGBIG) * dv.x);
            float p1 = __expf((S[nt][1] + (1.f - m0v.y) * NEGBIG) * dv.y);
            float p2 = __expf((S[nt][2] + (1.f - m1v.x) * NEGBIG) * dv.x);
            float p3 = __expf((S[nt][3] + (1.f - m1v.y) * NEGBIG) * dv.y);
            li0 += p0 + p1;
            li1 += p2 + p3;
            S[nt][0] = p0; S[nt][1] = p1; S[nt][2] = p2; S[nt][3] = p3;
        }

        // ---- O += P V  (P A-frags from S registers; uint2 B-frags) ----
        #pragma unroll
        for (int kc = 0; kc < 4; kc++) {
            unsigned pa_h[4], pa_l[4];
            #pragma unroll
            for (int j = 0; j < 4; j++) {
                float x = S[2 * kc + (j >> 1)][(j & 1) ? 2 : 0];
                float y = S[2 * kc + (j >> 1)][(j & 1) ? 3 : 1];
                float hx = bf16_hi_f(x), hy = bf16_hi_f(y);
                pa_h[j] = pack_bf2(hx, hy);
                pa_l[j] = pack_bf2(x - hx, y - hy);
            }
            #pragma unroll
            for (int nt = 0; nt < 8; nt++) {
                int base = (nt * 8 + g) * 36 + kc * 8 + tg;
                uint2 b0 = Vt2[base];
                uint2 b1 = Vt2[base + 4];
                MMA_BF16(O[nt], pa_h, b0.x, b1.x);
                MMA_BF16(O[nt], pa_h, b0.y, b1.y);
                MMA_BF16(O[nt], pa_l, b0.x, b1.x);
            }
        }
    }

    // ---- single li reduction over the 4 tg lanes ----
    #pragma unroll
    for (int off = 1; off <= 2; off <<= 1) {
        li0 += __shfl_xor_sync(0xffffffffu, li0, off);
        li1 += __shfl_xor_sync(0xffffffffu, li1, off);
    }

    // ---- epilogue: normalize and write ctx ----
    float inv0 = 1.f / li0, inv1 = 1.f / li1;
    #pragma unroll
    for (int nt = 0; nt < 8; nt++) {
        float2 r0, r1;
        r0.x = O[nt][0] * inv0; r0.y = O[nt][1] * inv0;
        r1.x = O[nt][2] * inv1; r1.y = O[nt][3] * inv1;
        *(float2*)&g_ctx[(size_t)(b * 1024 + qrow0 + g) * 512
                         + h * 64 + nt * 8 + 2 * tg] = r0;
        *(float2*)&g_ctx[(size_t)(b * 1024 + qrow0 + g + 8) * 512
                         + h * 64 + nt * 8 + 2 * tg] = r1;
    }
}

// ---------------------------------------------------------------------------
// Kernel 3: output projection (R12 version).
// ---------------------------------------------------------------------------
__global__ __launch_bounds__(256, 2) void oproj_kernel(
    const float* __restrict__ Wo,
    const float* __restrict__ bo,
    float* __restrict__ out)
{
    __shared__ __align__(16) unsigned Whi[64 * 72];
    __shared__ __align__(16) unsigned Wlo[64 * 72];

    const int tid  = threadIdx.x;
    const int wid  = tid >> 5;
    const int lane = tid & 31;
    const int g    = lane >> 2;
    const int tg   = lane & 3;
    const int mt = blockIdx.x;
    const int noff = blockIdx.y * 64;

    const int mrow0 = mt * 128 + wid * 16;
    const float* arow0 = &g_ctx[(size_t)(mrow0 + g) * 512];
    const float* arow1 = arow0 + 8 * 512;

    const int kp  = tid >> 2;
    const int n16 = (tid & 3) * 16;

    float C[8][4];
    #pragma unroll
    for (int nt = 0; nt < 8; nt++)
        #pragma unroll
        for (int j = 0; j < 4; j++) C[nt][j] = 0.f;

    #pragma unroll
    for (int s = 0; s < 4; s++) {
        __syncthreads();
        {
            const float* wr0 = &Wo[(size_t)(s * 128 + 2 * kp) * 256 + noff + n16];
            const float* wr1 = wr0 + 256;
            #pragma unroll
            for (int c = 0; c < 16; c += 4) {
                float4 w0 = *(const float4*)&wr0[c];
                float4 w1 = *(const float4*)&wr1[c];
                float h0x = bf16_hi_f(w0.x), h1x = bf16_hi_f(w1.x);
                float h0y = bf16_hi_f(w0.y), h1y = bf16_hi_f(w1.y);
                float h0z = bf16_hi_f(w0.z), h1z = bf16_hi_f(w1.z);
                float h0w = bf16_hi_f(w0.w), h1w = bf16_hi_f(w1.w);
                uint4 hi4, lo4;
                hi4.x = pack_bf2(h0x, h1x);
                hi4.y = pack_bf2(h0y, h1y);
                hi4.z = pack_bf2(h0z, h1z);
                hi4.w = pack_bf2(h0w, h1w);
                lo4.x = pack_bf2(w0.x - h0x, w1.x - h1x);
                lo4.y = pack_bf2(w0.y - h0y, w1.y - h1y);
                lo4.z = pack_bf2(w0.z - h0z, w1.z - h1z);
                lo4.w = pack_bf2(w0.w - h0w, w1.w - h1w);
                *(uint4*)&Whi[kp * 72 + n16 + c] = hi4;
                *(uint4*)&Wlo[kp * 72 + n16 + c] = lo4;
            }
        }
        __syncthreads();

        #pragma unroll
        for (int k0 = 0; k0 < 128; k0 += 32) {
            #pragma unroll
            for (int kc = 0; kc < 2; kc++) {
                unsigned ahi[4], alo[4];
                {
                    int col = s * 128 + k0 + kc * 16 + 2 * tg;
                    float2 a0 = *(const float2*)&arow0[col];
                    float2 a1 = *(const float2*)&arow1[col];
                    float2 a2 = *(const float2*)&arow0[col + 8];
                    float2 a3 = *(const float2*)&arow1[col + 8];
                    float hx, hy;
                    hx = bf16_hi_f(a0.x); hy = bf16_hi_f(a0.y);
                    ahi[0] = pack_bf2(hx, hy); alo[0] = pack_bf2(a0.x - hx, a0.y - hy);
                    hx = bf16_hi_f(a1.x); hy = bf16_hi_f(a1.y);
                    ahi[1] = pack_bf2(hx, hy); alo[1] = pack_bf2(a1.x - hx, a1.y - hy);
                    hx = bf16_hi_f(a2.x); hy = bf16_hi_f(a2.y);
                    ahi[2] = pack_bf2(hx, hy); alo[2] = pack_bf2(a2.x - hx, a2.y - hy);
                    hx = bf16_hi_f(a3.x); hy = bf16_hi_f(a3.y);
                    ahi[3] = pack_bf2(hx, hy); alo[3] = pack_bf2(a3.x - hx, a3.y - hy);
                }
                #pragma unroll
                for (int nt = 0; nt < 8; nt++) {
                    int base = (k0 / 2 + kc * 8 + tg) * 72 + nt * 8 + g;
                    unsigned b0h = Whi[base], b1h = Whi[base + 4 * 72];
                    unsigned b0l = Wlo[base], b1l = Wlo[base + 4 * 72];
                    MMA_BF16(C[nt], ahi, b0h, b1h);
                    MMA_BF16(C[nt], ahi, b0l, b1l);
                    MMA_BF16(C[nt], alo, b0h, b1h);
                }
            }
        }
    }

    #pragma unroll
    for (int nt = 0; nt < 8; nt++) {
        float2 bv = *(const float2*)&bo[noff + nt * 8 + 2 * tg];
        int m0 = mrow0 + g;
        float2 r0, r1;
        r0.x = C[nt][0] + bv.x; r0.y = C[nt][1] + bv.y;
        r1.x = C[nt][2] + bv.x; r1.y = C[nt][3] + bv.y;
        *(float2*)&out[(size_t)m0 * 256 + noff + nt * 8 + 2 * tg] = r0;
        *(float2*)&out[(size_t)(m0 + 8) * 256 + noff + nt * 8 + 2 * tg] = r1;
    }
}

// ---------------------------------------------------------------------------
extern "C" void kernel_launch(void* const* d_in, const int* in_sizes, int n_in,
                              void* d_out, int out_size)
{
    const float* X  = (const float*)d_in[0];
    const float* em = (const float*)d_in[1];
    const float* dw = (const float*)d_in[2];
    const float* Wq = (const float*)d_in[3];
    const float* Wk = (const float*)d_in[4];
    const float* Wv = (const float*)d_in[5];
    const float* Wo = (const float*)d_in[6];
    const float* bo = (const float*)d_in[7];
    float* out = (float*)d_out;

    qkv_kernel  <<<dim3(64, 8, 3), 256>>>(X, Wq, Wk, Wv);
    attn_kernel <<<dim3(8, 8, 8), 256>>>(em, dw);
    oproj_kernel<<<dim3(64, 4, 1), 256>>>(Wo, bo, out);
}